// round 6
// baseline (speedup 1.0000x reference)
#include <cuda_runtime.h>
#include <cuda_bf16.h>

#define FULL_MASK 0xFFFFFFFFu

constexpr int B_ROWS     = 16384;
constexpr int SEQ_L      = 50;
constexpr int N_SUBJECTS = 10000;
constexpr int N_ITER     = 13;      // 13 * 4 groups = 52 >= 50 positions

// Augmented premultiplied table: one 128B line per subject.
// aug[j] = { escore_j * emb_j  (quads 0..3),
//            (escore_j, 0,0,0) (quad 4),
//            zeros              (quads 5..7) }
// escore_j = exp(dot(emb_j, w) + b), with escore_0 forced to 0 (PAD row).
// Softmax without max-subtraction is exact: scores are O(0.1)
// (emb ~0.1*N, w ~0.25*N, D=16) -> no fp32 overflow; softmax shift-invariant.
__device__ __align__(128) float4 g_aug[N_SUBJECTS * 8];

__device__ __forceinline__ float dot4(float4 a, float4 b) {
    return a.x * b.x + a.y * b.y + a.z * b.z + a.w * b.w;
}

// ---------------- Prologue: build the augmented table ----------------
__global__ void __launch_bounds__(256)
aug_kernel(const float* __restrict__ subj_emb,
           const float* __restrict__ attn_w,
           const float* __restrict__ attn_b)
{
    const int j = blockIdx.x * blockDim.x + threadIdx.x;
    if (j >= N_SUBJECTS) return;

    const float4* wp = reinterpret_cast<const float4*>(attn_w);
    const float4 w0 = __ldg(wp + 0), w1 = __ldg(wp + 1),
                 w2 = __ldg(wp + 2), w3 = __ldg(wp + 3);

    const float4* ep = reinterpret_cast<const float4*>(subj_emb) + (size_t)j * 4;
    const float4 e0 = __ldg(ep + 0), e1 = __ldg(ep + 1),
                 e2 = __ldg(ep + 2), e3 = __ldg(ep + 3);

    const float s = dot4(e0, w0) + dot4(e1, w1) + dot4(e2, w2) + dot4(e3, w3)
                  + __ldg(attn_b);
    const float w = (j == 0) ? 0.0f : __expf(s);   // PAD row contributes nothing

    float4* dst = g_aug + (size_t)j * 8;
    dst[0] = make_float4(w * e0.x, w * e0.y, w * e0.z, w * e0.w);
    dst[1] = make_float4(w * e1.x, w * e1.y, w * e1.z, w * e1.w);
    dst[2] = make_float4(w * e2.x, w * e2.y, w * e2.z, w * e2.w);
    dst[3] = make_float4(w * e3.x, w * e3.y, w * e3.z, w * e3.w);
    dst[4] = make_float4(w, 0.f, 0.f, 0.f);
    dst[5] = make_float4(0.f, 0.f, 0.f, 0.f);
    dst[6] = make_float4(0.f, 0.f, 0.f, 0.f);
    dst[7] = make_float4(0.f, 0.f, 0.f, 0.f);
}

// ---------------- Main: warp per row, 4 groups x 8 lanes ----------------
// Group g handles positions p = it*4 + g. The 8 lanes of a group load the
// 8 quads of one table line -> 1 line (1 wavefront) per group per LDG.128.
// No masks, no scores, no expf in the loop: pure gather + add.
__global__ void __launch_bounds__(256)
scalar_pooler_kernel(
    const float* __restrict__ user_bias,
    const float* __restrict__ item_bias,
    const float* __restrict__ global_bias,
    const int*   __restrict__ user_idx,
    const int*   __restrict__ item_idx,
    const int*   __restrict__ fav,
    const int*   __restrict__ book,
    float*       __restrict__ out)
{
    const int row  = (blockIdx.x * blockDim.x + threadIdx.x) >> 5;
    const int lane = threadIdx.x & 31;
    const int grp  = lane >> 3;     // 0..3
    const int chk  = lane & 7;      // 0..7 (quad within the 128B line)
    if (row >= B_ROWS) return;

    const int* frow = fav  + (size_t)row * SEQ_L;
    const int* brow = book + (size_t)row * SEQ_L;

    // Coalesced index preload; OOB positions (>=50) read as 0 -> zero row.
    const int fu_lo = __ldg(frow + lane);
    const int fu_hi = (lane + 32 < SEQ_L) ? __ldg(frow + lane + 32) : 0;
    const int bk_lo = __ldg(brow + lane);
    const int bk_hi = (lane + 32 < SEQ_L) ? __ldg(brow + lane + 32) : 0;

    float4 au = make_float4(0.f, 0.f, 0.f, 0.f);
    float4 ai = make_float4(0.f, 0.f, 0.f, 0.f);

    #pragma unroll
    for (int it = 0; it < N_ITER; it++) {
        // p = it*4 + grp; for it>=8 take from the _hi register (src = p-32).
        const int src = (it < 8) ? (it * 4 + grp) : ((it - 8) * 4 + grp);
        const int iu = __shfl_sync(FULL_MASK, (it < 8) ? fu_lo : fu_hi, src);
        const int ib = __shfl_sync(FULL_MASK, (it < 8) ? bk_lo : bk_hi, src);

        const float4 eu = __ldg(g_aug + (size_t)iu * 8 + chk);
        const float4 eb = __ldg(g_aug + (size_t)ib * 8 + chk);

        au.x += eu.x;  au.y += eu.y;  au.z += eu.z;  au.w += eu.w;
        ai.x += eb.x;  ai.y += eb.y;  ai.z += eb.z;  ai.w += eb.w;
    }

    // Reduce au across the 4 groups (strides 8, 16). After this, lanes with
    // equal chk hold identical values: chk 0..3 = u numerator chunks,
    // chk 4 = (su, 0,0,0), chk 5..7 = 0.
    #pragma unroll
    for (int off = 8; off < 32; off <<= 1) {
        au.x += __shfl_xor_sync(FULL_MASK, au.x, off);
        au.y += __shfl_xor_sync(FULL_MASK, au.y, off);
        au.z += __shfl_xor_sync(FULL_MASK, au.z, off);
        au.w += __shfl_xor_sync(FULL_MASK, au.w, off);
    }

    // Unnormalized dot(u, i): ai is still group-partial, so each (group,
    // chunk) cell is counted exactly once; exclude the escore lanes.
    float r = (chk <= 3) ? dot4(au, ai) : 0.f;
    #pragma unroll
    for (int off = 16; off; off >>= 1)
        r += __shfl_xor_sync(FULL_MASK, r, off);

    // Denominators: si from ai.x at chk==4 lanes reduced across groups;
    // su already reduced inside au.x.
    float t = ai.x;
    t += __shfl_xor_sync(FULL_MASK, t, 8);
    t += __shfl_xor_sync(FULL_MASK, t, 16);

    const float su = __shfl_sync(FULL_MASK, au.x, 4);   // lane (g=0, chk=4)
    const float si = __shfl_sync(FULL_MASK, t,    4);

    if (lane == 0) {
        // All-pad row: su/si == 0 -> inv = 0 reproduces the reference
        // (pooled vector is the zero PAD embedding).
        const float inv_u = (su > 0.f) ? (1.0f / su) : 0.f;
        const float inv_i = (si > 0.f) ? (1.0f / si) : 0.f;
        out[row] = r * inv_u * inv_i
                 + __ldg(user_bias + __ldg(user_idx + row))
                 + __ldg(item_bias + __ldg(item_idx + row))
                 + __ldg(global_bias);
    }
}

extern "C" void kernel_launch(void* const* d_in, const int* in_sizes, int n_in,
                              void* d_out, int out_size)
{
    const float* subj_emb    = (const float*)d_in[0];
    const float* attn_w      = (const float*)d_in[1];
    const float* attn_b      = (const float*)d_in[2];
    const float* user_bias   = (const float*)d_in[3];
    const float* item_bias   = (const float*)d_in[4];
    const float* global_bias = (const float*)d_in[5];
    const int*   user_idx    = (const int*)d_in[6];
    const int*   item_idx    = (const int*)d_in[7];
    const int*   fav         = (const int*)d_in[8];
    const int*   book        = (const int*)d_in[9];
    float*       out         = (float*)d_out;

    aug_kernel<<<(N_SUBJECTS + 255) / 256, 256>>>(subj_emb, attn_w, attn_b);

    const int threads = 256;                       // 8 warps = 8 rows/block
    const int blocks  = (B_ROWS * 32) / threads;   // 2048
    scalar_pooler_kernel<<<blocks, threads>>>(
        user_bias, item_bias, global_bias,
        user_idx, item_idx, fav, book, out);
}

// round 7
// speedup vs baseline: 1.0015x; 1.0015x over previous
#include <cuda_runtime.h>
#include <cuda_bf16.h>

#define FULL_MASK 0xFFFFFFFFu

constexpr int B_ROWS     = 16384;
constexpr int SEQ_L      = 50;
constexpr int N_SUBJECTS = 10000;
constexpr int N_ITER     = 7;        // 7 * 8 groups = 56 >= 50 positions
constexpr int THREADS    = 512;      // 16 warps
constexpr int ROWS_PER_WARP = 4;
constexpr int ROWS_PER_BLOCK = 16 * ROWS_PER_WARP;   // 64

// pm[j] = escore_j * emb_j (16 fp32 = 64B row; row 0 is all zeros since
// escore_0 := 0 -> PAD / out-of-range positions contribute nothing).
// escore_j = exp(dot(emb_j, w) + b). Softmax without max-subtraction is
// exact here: scores are O(0.1) (emb ~0.1N, w ~0.25N, D=16) -> no overflow,
// and softmax is shift-invariant.
__device__ __align__(128) float4 g_pm[N_SUBJECTS * 4];
__device__ float g_escore[N_SUBJECTS];

__device__ __forceinline__ float dot4(float4 a, float4 b) {
    return a.x * b.x + a.y * b.y + a.z * b.z + a.w * b.w;
}

// ---------------- Prologue ----------------
__global__ void __launch_bounds__(256)
pm_kernel(const float* __restrict__ subj_emb,
          const float* __restrict__ attn_w,
          const float* __restrict__ attn_b)
{
    const int j = blockIdx.x * blockDim.x + threadIdx.x;
    if (j >= N_SUBJECTS) return;

    const float4* wp = reinterpret_cast<const float4*>(attn_w);
    const float4 w0 = __ldg(wp + 0), w1 = __ldg(wp + 1),
                 w2 = __ldg(wp + 2), w3 = __ldg(wp + 3);

    const float4* ep = reinterpret_cast<const float4*>(subj_emb) + (size_t)j * 4;
    const float4 e0 = __ldg(ep + 0), e1 = __ldg(ep + 1),
                 e2 = __ldg(ep + 2), e3 = __ldg(ep + 3);

    const float s = dot4(e0, w0) + dot4(e1, w1) + dot4(e2, w2) + dot4(e3, w3)
                  + __ldg(attn_b);
    const float w = (j == 0) ? 0.0f : __expf(s);

    float4* dst = g_pm + (size_t)j * 4;
    dst[0] = make_float4(w * e0.x, w * e0.y, w * e0.z, w * e0.w);
    dst[1] = make_float4(w * e1.x, w * e1.y, w * e1.z, w * e1.w);
    dst[2] = make_float4(w * e2.x, w * e2.y, w * e2.z, w * e2.w);
    dst[3] = make_float4(w * e3.x, w * e3.y, w * e3.z, w * e3.w);
    g_escore[j] = w;
}

// ---------------- Main ----------------
// Warp = 8 groups x 4 lanes; group g handles positions p = it*8+g, lane
// chunk c = lane&3 owns 16B of the 64B pm row (4 lanes/group share one
// 128B line -> 1 wavefront per group per LDG.128).
// Numerators: pure gather+FADD (premultiplied). Denominators: LDS from the
// block-shared 40KB escore table (no L1tex wavefronts).
__global__ void __launch_bounds__(THREADS)
scalar_pooler_kernel(
    const float* __restrict__ user_bias,
    const float* __restrict__ item_bias,
    const float* __restrict__ global_bias,
    const int*   __restrict__ user_idx,
    const int*   __restrict__ item_idx,
    const int*   __restrict__ fav,
    const int*   __restrict__ book,
    float*       __restrict__ out)
{
    __shared__ float s_escore[N_SUBJECTS];
    {
        const float4* src = reinterpret_cast<const float4*>(g_escore);
        float4* dst = reinterpret_cast<float4*>(s_escore);
        for (int i = threadIdx.x; i < N_SUBJECTS / 4; i += THREADS)
            dst[i] = __ldg(src + i);
    }
    __syncthreads();

    const int warp = threadIdx.x >> 5;
    const int lane = threadIdx.x & 31;
    const int grp  = lane >> 2;
    const int chk  = lane & 3;
    const bool hi_ok = (lane + 32) < SEQ_L;   // lanes 0..17

    const float4* pm = g_pm;
    const int row0 = blockIdx.x * ROWS_PER_BLOCK + warp * ROWS_PER_WARP;

    for (int r = 0; r < ROWS_PER_WARP; r++) {
        const int row = row0 + r;
        const int* frow = fav  + (size_t)row * SEQ_L;
        const int* brow = book + (size_t)row * SEQ_L;

        // Coalesced index preload (registers feed both gathers and denoms).
        const int f_lo = __ldg(frow + lane);
        const int f_hi = hi_ok ? __ldg(frow + lane + 32) : 0;
        const int b_lo = __ldg(brow + lane);
        const int b_hi = hi_ok ? __ldg(brow + lane + 32) : 0;

        // Denominator partials from smem (escore[0] == 0 -> PAD/OOB free).
        float su = s_escore[f_lo] + (hi_ok ? s_escore[f_hi] : 0.f);
        float si = s_escore[b_lo] + (hi_ok ? s_escore[b_hi] : 0.f);

        float4 au = make_float4(0.f, 0.f, 0.f, 0.f);
        float4 ai = make_float4(0.f, 0.f, 0.f, 0.f);

        #pragma unroll
        for (int it = 0; it < N_ITER; it++) {
            const int src = (it & 3) * 8 + grp;        // (it*8+grp) mod 32
            int iu = __shfl_sync(FULL_MASK, (it < 4) ? f_lo : f_hi, src);
            int ib = __shfl_sync(FULL_MASK, (it < 4) ? b_lo : b_hi, src);
            if (it == 6 && grp >= 2) { iu = 0; ib = 0; }   // p in [50,56)

            const float4 eu = __ldg(pm + (size_t)iu * 4 + chk);
            const float4 eb = __ldg(pm + (size_t)ib * 4 + chk);

            au.x += eu.x;  au.y += eu.y;  au.z += eu.z;  au.w += eu.w;
            ai.x += eb.x;  ai.y += eb.y;  ai.z += eb.z;  ai.w += eb.w;
        }

        // Denominators: full 32-lane butterfly.
        #pragma unroll
        for (int off = 16; off; off >>= 1) {
            su += __shfl_xor_sync(FULL_MASK, su, off);
            si += __shfl_xor_sync(FULL_MASK, si, off);
        }

        // Reduce u's chunk across the 8 groups (strides 4,8,16).
        #pragma unroll
        for (int off = 4; off < 32; off <<= 1) {
            au.x += __shfl_xor_sync(FULL_MASK, au.x, off);
            au.y += __shfl_xor_sync(FULL_MASK, au.y, off);
            au.z += __shfl_xor_sync(FULL_MASK, au.z, off);
            au.w += __shfl_xor_sync(FULL_MASK, au.w, off);
        }

        // dot(u, i): lane contributes dot(u_chunk[c], ai_partial[c, g]);
        // the 32-lane sum counts each (chunk, group) cell exactly once.
        float p = dot4(au, ai);
        #pragma unroll
        for (int off = 16; off; off >>= 1)
            p += __shfl_xor_sync(FULL_MASK, p, off);

        if (lane == 0) {
            // All-pad row: su/si == 0 -> inv = 0 matches the reference
            // (it pools the all-zero PAD embedding).
            const float inv_u = (su > 0.f) ? (1.0f / su) : 0.f;
            const float inv_i = (si > 0.f) ? (1.0f / si) : 0.f;
            out[row] = p * inv_u * inv_i
                     + __ldg(user_bias + __ldg(user_idx + row))
                     + __ldg(item_bias + __ldg(item_idx + row))
                     + __ldg(global_bias);
        }
    }
}

extern "C" void kernel_launch(void* const* d_in, const int* in_sizes, int n_in,
                              void* d_out, int out_size)
{
    const float* subj_emb    = (const float*)d_in[0];
    const float* attn_w      = (const float*)d_in[1];
    const float* attn_b      = (const float*)d_in[2];
    const float* user_bias   = (const float*)d_in[3];
    const float* item_bias   = (const float*)d_in[4];
    const float* global_bias = (const float*)d_in[5];
    const int*   user_idx    = (const int*)d_in[6];
    const int*   item_idx    = (const int*)d_in[7];
    const int*   fav         = (const int*)d_in[8];
    const int*   book        = (const int*)d_in[9];
    float*       out         = (float*)d_out;

    pm_kernel<<<(N_SUBJECTS + 255) / 256, 256>>>(subj_emb, attn_w, attn_b);

    const int blocks = B_ROWS / ROWS_PER_BLOCK;    // 256
    scalar_pooler_kernel<<<blocks, THREADS>>>(
        user_bias, item_bias, global_bias,
        user_idx, item_idx, fav, book, out);
}

// round 8
// speedup vs baseline: 1.2600x; 1.2581x over previous
#include <cuda_runtime.h>
#include <cuda_bf16.h>

#define FULL_MASK 0xFFFFFFFFu

constexpr int B_ROWS     = 16384;
constexpr int SEQ_L      = 50;
constexpr int N_SUBJECTS = 10000;
constexpr int N_ITER     = 13;      // 13 * 4 groups = 52 >= 50 positions

// Augmented bf16 table, one 64B row per subject:
//   bytes [0,32):  escore_j * emb_j  as 16 bf16
//   bytes [32,34): escore_j as bf16
//   bytes [34,64): zeros
// escore_j = exp(dot(emb_j, w) + b); escore_0 := 0 so PAD (idx 0) and
// out-of-range positions contribute 0 to numerator AND denominator.
// Softmax without max-subtraction is exact: scores are O(0.1)
// (emb ~0.1*N, w ~0.25*N, D=16) -> no fp32 overflow; shift-invariant.
__device__ __align__(128) uint4 g_tab[N_SUBJECTS * 4];

__device__ __forceinline__ float dot4(float4 a, float4 b) {
    return a.x * b.x + a.y * b.y + a.z * b.z + a.w * b.w;
}

// ---------------- Prologue: build augmented bf16 table ----------------
__global__ void __launch_bounds__(256)
tab_kernel(const float* __restrict__ subj_emb,
           const float* __restrict__ attn_w,
           const float* __restrict__ attn_b)
{
    const int j = blockIdx.x * blockDim.x + threadIdx.x;
    if (j >= N_SUBJECTS) return;

    const float4* wp = reinterpret_cast<const float4*>(attn_w);
    const float4 w0 = __ldg(wp + 0), w1 = __ldg(wp + 1),
                 w2 = __ldg(wp + 2), w3 = __ldg(wp + 3);

    const float4* ep = reinterpret_cast<const float4*>(subj_emb) + (size_t)j * 4;
    const float4 e0 = __ldg(ep + 0), e1 = __ldg(ep + 1),
                 e2 = __ldg(ep + 2), e3 = __ldg(ep + 3);

    const float s = dot4(e0, w0) + dot4(e1, w1) + dot4(e2, w2) + dot4(e3, w3)
                  + __ldg(attn_b);
    const float w = (j == 0) ? 0.0f : __expf(s);

    // Pack escore*emb as bf16 pairs.
    const float4 p0 = make_float4(w*e0.x, w*e0.y, w*e0.z, w*e0.w);
    const float4 p1 = make_float4(w*e1.x, w*e1.y, w*e1.z, w*e1.w);
    const float4 p2 = make_float4(w*e2.x, w*e2.y, w*e2.z, w*e2.w);
    const float4 p3 = make_float4(w*e3.x, w*e3.y, w*e3.z, w*e3.w);

    auto pack2 = [](float a, float b) -> unsigned {
        __nv_bfloat162 h = __floats2bfloat162_rn(a, b);
        return *reinterpret_cast<unsigned*>(&h);
    };

    uint4* dst = g_tab + (size_t)j * 4;
    dst[0] = make_uint4(pack2(p0.x,p0.y), pack2(p0.z,p0.w),
                        pack2(p1.x,p1.y), pack2(p1.z,p1.w));
    dst[1] = make_uint4(pack2(p2.x,p2.y), pack2(p2.z,p2.w),
                        pack2(p3.x,p3.y), pack2(p3.z,p3.w));
    dst[2] = make_uint4(pack2(w, 0.f), 0u, 0u, 0u);   // escore slot
    dst[3] = make_uint4(0u, 0u, 0u, 0u);
}

// ---------------- Main: warp per row, 4 groups x 8 lanes ----------------
// Group g handles positions p = it*4 + g. Lane c = lane&7:
//   c 0..3 -> LDG.64 of premult bf16 chunk c (8B = 4 values)
//   c 4..7 -> LDG.64 at offset 32 -> [escore, 0, 0, 0]
// All 8 lanes hit ONE 64B row (1 line) -> 4 wavefronts per LDG instruction.
// No expf / scores / masks in the loop: gather + cvt + add only.
__global__ void __launch_bounds__(256)
scalar_pooler_kernel(
    const float* __restrict__ user_bias,
    const float* __restrict__ item_bias,
    const float* __restrict__ global_bias,
    const int*   __restrict__ user_idx,
    const int*   __restrict__ item_idx,
    const int*   __restrict__ fav,
    const int*   __restrict__ book,
    float*       __restrict__ out)
{
    const int row  = (blockIdx.x * blockDim.x + threadIdx.x) >> 5;
    const int lane = threadIdx.x & 31;
    const int grp  = lane >> 3;                    // 0..3
    const int c    = lane & 7;                     // 0..7
    if (row >= B_ROWS) return;

    const int offc = (c < 4) ? c * 8 : 32;         // byte offset within row
    const char* tab = reinterpret_cast<const char*>(g_tab);

    const int* frow = fav  + (size_t)row * SEQ_L;
    const int* brow = book + (size_t)row * SEQ_L;

    // Coalesced index preload; OOB (>=50) reads as 0 -> zero table row.
    const int f_lo = __ldg(frow + lane);
    const int f_hi = (lane + 32 < SEQ_L) ? __ldg(frow + lane + 32) : 0;
    const int b_lo = __ldg(brow + lane);
    const int b_hi = (lane + 32 < SEQ_L) ? __ldg(brow + lane + 32) : 0;

    float4 au = make_float4(0.f, 0.f, 0.f, 0.f);
    float4 ai = make_float4(0.f, 0.f, 0.f, 0.f);

    #pragma unroll
    for (int it = 0; it < N_ITER; it++) {
        // p = it*4 + grp; src register/lane chosen at compile time per iter.
        const int src = (it < 8) ? (it * 4 + grp) : ((it - 8) * 4 + grp);
        const int iu = __shfl_sync(FULL_MASK, (it < 8) ? f_lo : f_hi, src);
        const int ib = __shfl_sync(FULL_MASK, (it < 8) ? b_lo : b_hi, src);

        const uint2 ru = __ldg(reinterpret_cast<const uint2*>(tab + (size_t)iu * 64 + offc));
        const uint2 rb = __ldg(reinterpret_cast<const uint2*>(tab + (size_t)ib * 64 + offc));

        const float2 u0 = __bfloat1622float2(*reinterpret_cast<const __nv_bfloat162*>(&ru.x));
        const float2 u1 = __bfloat1622float2(*reinterpret_cast<const __nv_bfloat162*>(&ru.y));
        const float2 v0 = __bfloat1622float2(*reinterpret_cast<const __nv_bfloat162*>(&rb.x));
        const float2 v1 = __bfloat1622float2(*reinterpret_cast<const __nv_bfloat162*>(&rb.y));

        au.x += u0.x;  au.y += u0.y;  au.z += u1.x;  au.w += u1.y;
        ai.x += v0.x;  ai.y += v0.y;  ai.z += v1.x;  ai.w += v1.y;
    }

    // Reduce au across the 4 groups (lane = grp*8 + c; strides 8, 16).
    // Afterwards: c 0..3 hold u numerator chunks, c==4 holds (su,0,0,0).
    #pragma unroll
    for (int off = 8; off < 32; off <<= 1) {
        au.x += __shfl_xor_sync(FULL_MASK, au.x, off);
        au.y += __shfl_xor_sync(FULL_MASK, au.y, off);
        au.z += __shfl_xor_sync(FULL_MASK, au.z, off);
        au.w += __shfl_xor_sync(FULL_MASK, au.w, off);
    }

    // Unnormalized dot(u, i): ai is still per-(group, chunk) partial, so the
    // 32-lane sum counts each cell exactly once; exclude escore lanes.
    float r = (c < 4) ? dot4(au, ai) : 0.f;
    #pragma unroll
    for (int off = 16; off; off >>= 1)
        r += __shfl_xor_sync(FULL_MASK, r, off);

    // Denominators: si = group-reduced ai.x at c==4; su already in au.x.
    float t = ai.x;
    t += __shfl_xor_sync(FULL_MASK, t, 8);
    t += __shfl_xor_sync(FULL_MASK, t, 16);

    const float su = __shfl_sync(FULL_MASK, au.x, 4);
    const float si = __shfl_sync(FULL_MASK, t,    4);

    if (lane == 0) {
        // All-pad row: su/si == 0 -> inv = 0 matches the reference
        // (it pools the all-zero PAD embedding row).
        const float inv_u = (su > 0.f) ? (1.0f / su) : 0.f;
        const float inv_i = (si > 0.f) ? (1.0f / si) : 0.f;
        out[row] = r * inv_u * inv_i
                 + __ldg(user_bias + __ldg(user_idx + row))
                 + __ldg(item_bias + __ldg(item_idx + row))
                 + __ldg(global_bias);
    }
}

extern "C" void kernel_launch(void* const* d_in, const int* in_sizes, int n_in,
                              void* d_out, int out_size)
{
    const float* subj_emb    = (const float*)d_in[0];
    const float* attn_w      = (const float*)d_in[1];
    const float* attn_b      = (const float*)d_in[2];
    const float* user_bias   = (const float*)d_in[3];
    const float* item_bias   = (const float*)d_in[4];
    const float* global_bias = (const float*)d_in[5];
    const int*   user_idx    = (const int*)d_in[6];
    const int*   item_idx    = (const int*)d_in[7];
    const int*   fav         = (const int*)d_in[8];
    const int*   book        = (const int*)d_in[9];
    float*       out         = (float*)d_out;

    tab_kernel<<<(N_SUBJECTS + 255) / 256, 256>>>(subj_emb, attn_w, attn_b);

    const int threads = 256;                       // 8 warps = 8 rows/block
    const int blocks  = (B_ROWS * 32) / threads;   // 2048
    scalar_pooler_kernel<<<blocks, threads>>>(
        user_bias, item_bias, global_bias,
        user_idx, item_idx, fav, book, out);
}